// round 14
// baseline (speedup 1.0000x reference)
#include <cuda_runtime.h>
#include <cuda_fp16.h>
#include <math.h>
#include <cstdint>

// ---------------------------------------------------------------------------
// PrisonerDilemmaEngine — R12: XOR-swizzled smem, 3-stage cp.async pipeline,
// single sync/chunk, G stored f16. fp16 hi/lo 3-term mma.sync.
// ---------------------------------------------------------------------------

#define NCELLS 131072
#define FS     16384
#define DC     4096

// hi/lo f16 scratch (activations)
__device__ __align__(16) __half g_hid_hi[(size_t)NCELLS * 256];
__device__ __align__(16) __half g_hid_lo[(size_t)NCELLS * 256];
__device__ __align__(16) __half g_H1_hi[(size_t)NCELLS * 256];
__device__ __align__(16) __half g_H1_lo[(size_t)NCELLS * 256];
__device__ __align__(16) __half g_out_hi[(size_t)NCELLS * 128];
__device__ __align__(16) __half g_out_lo[(size_t)NCELLS * 128];
// hi/lo f16 weights
__device__ __align__(16) __half g_w1_hi[256 * 256];
__device__ __align__(16) __half g_w1_lo[256 * 256];
__device__ __align__(16) __half g_w2_hi[128 * 256];
__device__ __align__(16) __half g_w2_lo[128 * 256];
__device__ __align__(16) __half g_gw_hi[1024 * 384];
__device__ __align__(16) __half g_gw_lo[1024 * 384];
__device__ float g_gb[1024];
__device__ float g_wcol2[1024];
// gate preactivations in f16 (abs err ~3e-5 on ~0.15-magnitude preacts)
__device__ __align__(16) __half g_G[(size_t)NCELLS * 1024];  // [rsum|zsum|gi_n|gh_n]
// f32 scratch
__device__ __align__(16) float g_newh[(size_t)NCELLS * 256];
__device__ __align__(16) float g_tension[NCELLS];
__device__ float g_xwb[256];
__device__ float g_fsum[2048];
__device__ float g_fdcsum[2048];
__device__ float g_fmean[2048];
__device__ float g_globalop[256];
__device__ float g_gmean[256];
__device__ float g_sumexp;
__device__ float g_sumtens;
__device__ float g_sumexpout[128];

// ---------------------------------------------------------------------------
// PTX helpers
// ---------------------------------------------------------------------------
__device__ __forceinline__ unsigned sptr(const void* p) {
    return (unsigned)__cvta_generic_to_shared(p);
}
#define CP16(dst, src) \
    asm volatile("cp.async.ca.shared.global [%0], [%1], 16;" :: "r"(dst), "l"(src))
#define CPCOMMIT() asm volatile("cp.async.commit_group;" ::: "memory")
#define CPWAIT(n)  asm volatile("cp.async.wait_group %0;" :: "n"(n) : "memory")
#define LDSM4(r0, r1, r2, r3, addr)                                              \
    asm volatile("ldmatrix.sync.aligned.m8n8.x4.shared.b16 {%0,%1,%2,%3}, [%4];" \
                 : "=r"(r0), "=r"(r1), "=r"(r2), "=r"(r3) : "r"(addr))
#define MMA_F16(d, a0_, a1_, a2_, a3_, b0_, b1_)                             \
    asm volatile("mma.sync.aligned.m16n8k16.row.col.f32.f16.f16.f32 "        \
                 "{%0,%1,%2,%3},{%4,%5,%6,%7},{%8,%9},{%0,%1,%2,%3};"        \
                 : "+f"(d[0]), "+f"(d[1]), "+f"(d[2]), "+f"(d[3])            \
                 : "r"(a0_), "r"(a1_), "r"(a2_), "r"(a3_),                   \
                   "r"(b0_), "r"(b1_))

__device__ __forceinline__ void split_h2(float a, float b, __half2& hi, __half2& lo) {
    __half ha = __float2half_rn(a), hb = __float2half_rn(b);
    hi = __halves2half2(ha, hb);
    lo = __halves2half2(__float2half_rn(a - __half2float(ha)),
                        __float2half_rn(b - __half2float(hb)));
}

// swizzled byte offset inside an 8KB tile (128 rows x 32 halfs):
// 16B-slot g in 0..3, slot' = g ^ ((row>>1)&3)  -> conflict-free LDSM + cp.async
__device__ __forceinline__ int swzoff(int row, int g) {
    return row * 64 + ((g ^ ((row >> 1) & 3)) << 4);
}

#define TILEB  8192
#define STAGEB 32768   // Ah | Al | Bh | Bl

// ---------------------------------------------------------------------------
// K0: zero accumulators + xwb
// ---------------------------------------------------------------------------
__global__ void k0_init(const float* __restrict__ x,
                        const float* __restrict__ a_w1, const float* __restrict__ a_b1,
                        const float* __restrict__ g_w1, const float* __restrict__ g_b1) {
    int tid = threadIdx.x;
    if (tid == 0) { g_sumexp = 0.f; g_sumtens = 0.f; }
    if (tid < 128) g_sumexpout[tid] = 0.f;
    for (int k = tid; k < 2048; k += 256) { g_fsum[k] = 0.f; g_fdcsum[k] = 0.f; }
    int r = tid;
    const float* w = (r < 128) ? (a_w1 + (size_t)r * 384) : (g_w1 + (size_t)(r - 128) * 384);
    float s = (r < 128) ? a_b1[r] : g_b1[r - 128];
    #pragma unroll 4
    for (int k = 0; k < 128; k++) s += x[k] * w[k];
    g_xwb[r] = s;
}

// ---------------------------------------------------------------------------
// kconv: weights -> hi/lo f16; gates bias + tension column
// ---------------------------------------------------------------------------
__global__ void kconv(const float* __restrict__ a_w1, const float* __restrict__ g_w1,
                      const float* __restrict__ a_w2, const float* __restrict__ g_w2,
                      const float* __restrict__ wih,  const float* __restrict__ whh,
                      const float* __restrict__ bih,  const float* __restrict__ bhh) {
    int t = blockIdx.x * 256 + threadIdx.x;
    if (t < 65536) {
        int r = t >> 8, k = t & 255;
        float v = (r < 128) ? a_w1[(size_t)r * 384 + 128 + k]
                            : g_w1[(size_t)(r - 128) * 384 + 128 + k];
        __half h = __float2half_rn(v);
        g_w1_hi[t] = h;
        g_w1_lo[t] = __float2half_rn(v - __half2float(h));
        return;
    }
    t -= 65536;
    if (t < 32768) {
        int r = t >> 8, k = t & 255;
        float v = (k < 128) ? a_w2[(size_t)r * 128 + k] : -g_w2[(size_t)r * 128 + (k - 128)];
        __half h = __float2half_rn(v);
        g_w2_hi[t] = h;
        g_w2_lo[t] = __float2half_rn(v - __half2float(h));
        return;
    }
    t -= 32768;
    if (t < 393216) {
        int r = t / 384, k = t - r * 384;
        float v = 0.f;
        if (r < 512)       v = (k < 128) ? wih[(size_t)r * 129 + k] : whh[(size_t)r * 256 + (k - 128)];
        else if (r < 768)  { if (k < 128) v = wih[(size_t)r * 129 + k]; }
        else               { if (k < 256) v = whh[(size_t)(r - 256) * 256 + k]; }
        __half h = __float2half_rn(v);
        g_gw_hi[t] = h;
        g_gw_lo[t] = __float2half_rn(v - __half2float(h));
        return;
    }
    t -= 393216;
    if (t < 1024) {
        int r = t;
        float b;
        if (r < 512)      b = bih[r] + bhh[r];
        else if (r < 768) b = bih[r];
        else              b = bhh[r - 256];
        g_gb[r] = b;
        g_wcol2[r] = (r < 768) ? wih[(size_t)r * 129 + 128] : 0.f;
    }
}

// ---------------------------------------------------------------------------
// khh: hiddens f32 -> hi/lo f16
// ---------------------------------------------------------------------------
__global__ void __launch_bounds__(256) khh(const float* __restrict__ hiddens) {
    size_t base = ((size_t)blockIdx.x * 256 + threadIdx.x) * 8;
    float4 a = *(const float4*)(hiddens + base);
    float4 b = *(const float4*)(hiddens + base + 4);
    __half2 hi[4], lo[4];
    split_h2(a.x, a.y, hi[0], lo[0]);
    split_h2(a.z, a.w, hi[1], lo[1]);
    split_h2(b.x, b.y, hi[2], lo[2]);
    split_h2(b.z, b.w, hi[3], lo[3]);
    *(uint4*)(g_hid_hi + base) = *(uint4*)hi;
    *(uint4*)(g_hid_lo + base) = *(uint4*)lo;
}

// ---------------------------------------------------------------------------
// stage loader: A/B tiles 128x32 f16 hi+lo, swizzled, pure cp.async
// ---------------------------------------------------------------------------
template <int KID>
__device__ __forceinline__ void load_stage(char* base, int k0, int c0, int m0, int grp) {
    const int tid = threadIdx.x;
    #pragma unroll
    for (int i = 0; i < 2; i++) {
        int q = tid + 256 * i;
        int row = q >> 2, g = q & 3, c8 = g * 8;
        const __half *sh, *sl;
        if (KID == 1) {
            size_t off = (size_t)(c0 + row) * 256 + k0 + c8;
            sh = g_hid_hi + off; sl = g_hid_lo + off;
        } else if (KID == 2) {
            size_t off = (size_t)(c0 + row) * 256 + k0 + c8;
            sh = g_H1_hi + off; sl = g_H1_lo + off;
        } else {
            int kk = k0 + c8;
            if (grp < 4) {
                if (kk < 128) { size_t off = (size_t)(c0 + row) * 128 + kk; sh = g_out_hi + off; sl = g_out_lo + off; }
                else          { size_t off = (size_t)(c0 + row) * 256 + (kk - 128); sh = g_hid_hi + off; sl = g_hid_lo + off; }
            } else if (grp < 6) { size_t off = (size_t)(c0 + row) * 128 + kk; sh = g_out_hi + off; sl = g_out_lo + off; }
            else                { size_t off = (size_t)(c0 + row) * 256 + kk; sh = g_hid_hi + off; sl = g_hid_lo + off; }
        }
        int d = swzoff(row, g);
        CP16(sptr(base + d), sh);
        CP16(sptr(base + TILEB + d), sl);
    }
    #pragma unroll
    for (int i = 0; i < 2; i++) {
        int q = tid + 256 * i;
        int row = q >> 2, g = q & 3, c8 = g * 8;
        size_t off;
        const __half *sh, *sl;
        if (KID == 1)      { off = (size_t)(m0 + row) * 256 + k0 + c8; sh = g_w1_hi + off; sl = g_w1_lo + off; }
        else if (KID == 2) { off = (size_t)row * 256 + k0 + c8;        sh = g_w2_hi + off; sl = g_w2_lo + off; }
        else               { off = (size_t)(m0 + row) * 384 + k0 + c8; sh = g_gw_hi + off; sl = g_gw_lo + off; }
        int d = swzoff(row, g);
        CP16(sptr(base + 2 * TILEB + d), sh);
        CP16(sptr(base + 3 * TILEB + d), sl);
    }
}

// ---------------------------------------------------------------------------
// Unified hi/lo f16 GEMM: 128x128 tile, 8 warps (4 rw x 2 cw), warp 32x64,
// K-chunk 32, 3-stage pipeline, ONE sync per chunk, 3-term MMA.
// KID: 1=layer1(relu->H1 hi/lo)  2=layer2(out,tension,softmax)  3=gates->G f16
// ---------------------------------------------------------------------------
template <int KID>
__global__ void __launch_bounds__(256, 2) gemm_hl(const float* __restrict__ B0,
                                                  const float* __restrict__ B1) {
    extern __shared__ __align__(16) char dynb[];
    __shared__ float s_b[128], s_aux[128], s_row[128], s_w[128], s_wout[128];

    const int tid = threadIdx.x, lane = tid & 31, warp = tid >> 5;
    const int rw = warp & 3, cw = warp >> 2;
    const int m0 = blockIdx.x * 128, c0 = blockIdx.y * 128;
    const int grp = (KID == 3) ? blockIdx.x : 0;
    int KD = 256;
    if (KID == 3) KD = (grp < 4) ? 384 : ((grp < 6) ? 128 : 256);
    const int NC = KD >> 5;

    if (tid < 128) {
        if (KID == 1) s_b[tid] = g_xwb[m0 + tid];
        if (KID == 2) { s_b[tid] = B0[tid] - B1[tid]; s_row[tid] = 0.f; s_wout[tid] = 0.f; }
        if (KID == 3) {
            s_b[tid] = g_gb[m0 + tid];
            s_w[tid] = g_wcol2[m0 + tid];
            s_aux[tid] = g_tension[c0 + tid];
        }
    }

    float acc[2][8][4];
    #pragma unroll
    for (int mt = 0; mt < 2; mt++)
        #pragma unroll
        for (int nq = 0; nq < 8; nq++)
            #pragma unroll
            for (int e = 0; e < 4; e++) acc[mt][nq][e] = 0.f;

    load_stage<KID>(dynb, 0, c0, m0, grp);
    CPCOMMIT();
    load_stage<KID>(dynb + STAGEB, 32, c0, m0, grp);
    CPCOMMIT();

    const int a_r = (lane & 7) + ((lane >> 3) & 1) * 8;
    const int ag = (lane >> 4) & 1;
    const int b_r = (lane & 7) + (((lane >> 3) & 2) << 2);
    const int bg = (lane >> 3) & 1;

    for (int c = 0; c < NC; c++) {
        if (c + 1 < NC) { CPWAIT(1); } else { CPWAIT(0); }
        __syncthreads();
        if (c + 2 < NC) {
            load_stage<KID>(dynb + ((c + 2) % 3) * STAGEB, (c + 2) * 32, c0, m0, grp);
            CPCOMMIT();
        }
        char* st = dynb + (c % 3) * STAGEB;
        #pragma unroll
        for (int kh = 0; kh < 2; kh++) {
            unsigned ah[2][4], al[2][4];
            #pragma unroll
            for (int mt = 0; mt < 2; mt++) {
                int off = swzoff(rw * 32 + mt * 16 + a_r, kh * 2 + ag);
                LDSM4(ah[mt][0], ah[mt][1], ah[mt][2], ah[mt][3], sptr(st + off));
                LDSM4(al[mt][0], al[mt][1], al[mt][2], al[mt][3], sptr(st + TILEB + off));
            }
            #pragma unroll
            for (int nt = 0; nt < 4; nt++) {
                unsigned bh[4], bl[4];
                int off = swzoff(cw * 64 + nt * 16 + b_r, kh * 2 + bg);
                LDSM4(bh[0], bh[1], bh[2], bh[3], sptr(st + 2 * TILEB + off));
                LDSM4(bl[0], bl[1], bl[2], bl[3], sptr(st + 3 * TILEB + off));
                #pragma unroll
                for (int mt = 0; mt < 2; mt++) {
                    MMA_F16(acc[mt][2 * nt], ah[mt][0], ah[mt][1], ah[mt][2], ah[mt][3], bh[0], bh[1]);
                    MMA_F16(acc[mt][2 * nt], al[mt][0], al[mt][1], al[mt][2], al[mt][3], bh[0], bh[1]);
                    MMA_F16(acc[mt][2 * nt], ah[mt][0], ah[mt][1], ah[mt][2], ah[mt][3], bl[0], bl[1]);
                    MMA_F16(acc[mt][2 * nt + 1], ah[mt][0], ah[mt][1], ah[mt][2], ah[mt][3], bh[2], bh[3]);
                    MMA_F16(acc[mt][2 * nt + 1], al[mt][0], al[mt][1], al[mt][2], al[mt][3], bh[2], bh[3]);
                    MMA_F16(acc[mt][2 * nt + 1], ah[mt][0], ah[mt][1], ah[mt][2], ah[mt][3], bl[2], bl[3]);
                }
            }
        }
    }

    // ------------------- epilogue -------------------
    const int rowb = c0 + rw * 32 + (lane >> 2);
    const int colb = cw * 64 + 2 * (lane & 3);

    if (KID == 1) {
        #pragma unroll
        for (int mt = 0; mt < 2; mt++) {
            int row0 = rowb + mt * 16, row1 = row0 + 8;
            #pragma unroll
            for (int nq = 0; nq < 8; nq++) {
                int col = colb + nq * 8;
                float b0v = s_b[col], b1v = s_b[col + 1];
                __half2 hi, lo;
                split_h2(fmaxf(acc[mt][nq][0] + b0v, 0.f), fmaxf(acc[mt][nq][1] + b1v, 0.f), hi, lo);
                *(__half2*)&g_H1_hi[(size_t)row0 * 256 + m0 + col] = hi;
                *(__half2*)&g_H1_lo[(size_t)row0 * 256 + m0 + col] = lo;
                split_h2(fmaxf(acc[mt][nq][2] + b0v, 0.f), fmaxf(acc[mt][nq][3] + b1v, 0.f), hi, lo);
                *(__half2*)&g_H1_hi[(size_t)row1 * 256 + m0 + col] = hi;
                *(__half2*)&g_H1_lo[(size_t)row1 * 256 + m0 + col] = lo;
            }
        }
    } else if (KID == 3) {
        #pragma unroll
        for (int mt = 0; mt < 2; mt++) {
            int row0 = rowb + mt * 16, row1 = row0 + 8;
            float t0 = s_aux[row0 - c0], t1 = s_aux[row1 - c0];
            #pragma unroll
            for (int nq = 0; nq < 8; nq++) {
                int col = colb + nq * 8;
                float b0v = s_b[col], b1v = s_b[col + 1];
                float w0c = s_w[col], w1c = s_w[col + 1];
                *(__half2*)&g_G[(size_t)row0 * 1024 + m0 + col] =
                    __floats2half2_rn(acc[mt][nq][0] + b0v + t0 * w0c, acc[mt][nq][1] + b1v + t0 * w1c);
                *(__half2*)&g_G[(size_t)row1 * 1024 + m0 + col] =
                    __floats2half2_rn(acc[mt][nq][2] + b0v + t1 * w0c, acc[mt][nq][3] + b1v + t1 * w1c);
            }
        }
    } else {  // KID == 2
        float ss0[2] = {0.f, 0.f}, ss1[2] = {0.f, 0.f};
        #pragma unroll
        for (int mt = 0; mt < 2; mt++) {
            int row0 = rowb + mt * 16, row1 = row0 + 8;
            #pragma unroll
            for (int nq = 0; nq < 8; nq++) {
                int col = colb + nq * 8;
                float b0v = s_b[col], b1v = s_b[col + 1];
                float v0 = acc[mt][nq][0] + b0v, v1 = acc[mt][nq][1] + b1v;
                float v2 = acc[mt][nq][2] + b0v, v3 = acc[mt][nq][3] + b1v;
                acc[mt][nq][0] = v0; acc[mt][nq][1] = v1;
                acc[mt][nq][2] = v2; acc[mt][nq][3] = v3;
                ss0[mt] += v0 * v0 + v1 * v1;
                ss1[mt] += v2 * v2 + v3 * v3;
                __half2 hi, lo;
                split_h2(v0, v1, hi, lo);
                *(__half2*)&g_out_hi[(size_t)row0 * 128 + col] = hi;
                *(__half2*)&g_out_lo[(size_t)row0 * 128 + col] = lo;
                split_h2(v2, v3, hi, lo);
                *(__half2*)&g_out_hi[(size_t)row1 * 128 + col] = hi;
                *(__half2*)&g_out_lo[(size_t)row1 * 128 + col] = lo;
            }
        }
        #pragma unroll
        for (int mt = 0; mt < 2; mt++) {
            #pragma unroll
            for (int o = 1; o <= 2; o <<= 1) {
                ss0[mt] += __shfl_xor_sync(0xffffffffu, ss0[mt], o);
                ss1[mt] += __shfl_xor_sync(0xffffffffu, ss1[mt], o);
            }
            if ((lane & 3) == 0) {
                atomicAdd(&s_row[rw * 32 + mt * 16 + (lane >> 2)], ss0[mt]);
                atomicAdd(&s_row[rw * 32 + mt * 16 + (lane >> 2) + 8], ss1[mt]);
            }
        }
        __syncthreads();
        if (tid < 128) {
            float t = s_row[tid] * 0.0078125f;
            g_tension[c0 + tid] = t;
            float w = __expf(t);
            s_w[tid] = w;
            float se = w, st = t;
            #pragma unroll
            for (int o = 16; o > 0; o >>= 1) {
                se += __shfl_xor_sync(0xffffffffu, se, o);
                st += __shfl_xor_sync(0xffffffffu, st, o);
            }
            if (lane == 0) { atomicAdd(&g_sumexp, se); atomicAdd(&g_sumtens, st); }
        }
        __syncthreads();
        float pw[16];
        #pragma unroll
        for (int j = 0; j < 16; j++) pw[j] = 0.f;
        #pragma unroll
        for (int mt = 0; mt < 2; mt++) {
            int rl0 = rw * 32 + mt * 16 + (lane >> 2);
            float w0 = s_w[rl0], w1 = s_w[rl0 + 8];
            #pragma unroll
            for (int nq = 0; nq < 8; nq++) {
                pw[2 * nq]     += w0 * acc[mt][nq][0] + w1 * acc[mt][nq][2];
                pw[2 * nq + 1] += w0 * acc[mt][nq][1] + w1 * acc[mt][nq][3];
            }
        }
        #pragma unroll
        for (int j = 0; j < 16; j++)
            #pragma unroll
            for (int o = 4; o <= 16; o <<= 1) pw[j] += __shfl_xor_sync(0xffffffffu, pw[j], o);
        if (lane < 4) {
            #pragma unroll
            for (int nq = 0; nq < 8; nq++) {
                atomicAdd(&s_wout[cw * 64 + nq * 8 + 2 * lane], pw[2 * nq]);
                atomicAdd(&s_wout[cw * 64 + nq * 8 + 2 * lane + 1], pw[2 * nq + 1]);
            }
        }
        __syncthreads();
        if (tid < 128) atomicAdd(&g_sumexpout[tid], s_wout[tid]);
    }
}

// ---------------------------------------------------------------------------
// k3c: GRU gates from G (f16) -> newh + faction sums
// ---------------------------------------------------------------------------
__device__ __forceinline__ float sigmoidf_(float x) { return 1.f / (1.f + __expf(-x)); }

__global__ void __launch_bounds__(256) k3c_gates(const float* __restrict__ hiddens,
                                                 const float* __restrict__ payoffs) {
    const int c0 = blockIdx.x * 128;
    const int j = threadIdx.x;
    const int f = c0 >> 14;
    const bool is_dc = (c0 & (FS - 1)) < DC;
    float lsum = 0.f;
    for (int ii = 0; ii < 128; ii++) {
        int i = c0 + ii;
        const __half* gp = g_G + (size_t)i * 1024;
        float gr  = __half2float(gp[j]);
        float gz  = __half2float(gp[256 + j]);
        float gin = __half2float(gp[512 + j]);
        float ghn = __half2float(gp[768 + j]);
        float rg = sigmoidf_(gr);
        float zg = sigmoidf_(gz);
        float ng = tanhf(gin + rg * ghn);
        float h = hiddens[(size_t)i * 256 + j];
        float v = (1.f - zg) * ng + zg * h;
        v *= (0.9f + 0.02f * payoffs[i]);
        v = fminf(fmaxf(v, -10.f), 10.f);
        g_newh[(size_t)i * 256 + j] = v;
        lsum += v;
    }
    atomicAdd(&g_fsum[f * 256 + j], lsum);
    if (is_dc) atomicAdd(&g_fdcsum[f * 256 + j], lsum);
}

// ---------------------------------------------------------------------------
// k4: faction means, global_op, analytic gmean, pred, avg_tension
// ---------------------------------------------------------------------------
__global__ void k4_small(const int* __restrict__ step,
                         const float* __restrict__ head_w,
                         const float* __restrict__ head_b,
                         float* __restrict__ out) {
    const int j = threadIdx.x;
    float fs[8], fm[8];
    float gop = 0.f, total = 0.f;
    #pragma unroll
    for (int f = 0; f < 8; f++) {
        fs[f] = g_fsum[f * 256 + j];
        fm[f] = fs[f] * (1.f / 16384.f);
        gop += fm[f];
        total += fs[f];
    }
    gop *= 0.125f;
    if (*step > 5) {
        #pragma unroll
        for (int f = 0; f < 8; f++) {
            float ssdc = 0.85f * g_fdcsum[f * 256 + j] + 0.15f * 4096.f * fm[f];
            total += 0.15f * (4096.f * gop - ssdc);
        }
    }
    g_gmean[j] = total * (1.f / 131072.f);
    g_globalop[j] = gop;
    #pragma unroll
    for (int f = 0; f < 8; f++) g_fmean[f * 256 + j] = fm[f];

    if (j < 128) {
        float inv = 1.0f / g_sumexp;
        float a = head_b[j];
        #pragma unroll 4
        for (int q = 0; q < 128; q++) a += head_w[(size_t)j * 128 + q] * (g_sumexpout[q] * inv);
        out[j] = a;
    }
    if (j == 0) out[128] = g_sumtens * (1.f / 131072.f);
}

// ---------------------------------------------------------------------------
// threefry2x32 partitionable: counter (0,e), key (0,42), bits = out0^out1
// ---------------------------------------------------------------------------
__device__ __forceinline__ float threefry_normal(unsigned e) {
    unsigned x0 = 0u, x1 = e;
    const unsigned ks0 = 0u, ks1 = 42u, ks2 = 0u ^ 42u ^ 0x1BD11BDAu;
    x0 += ks0; x1 += ks1;
#define TF_ROT(v, r) (((v) << (r)) | ((v) >> (32 - (r))))
#define TF_R4(a, b, c, d)                                        \
    x0 += x1; x1 = TF_ROT(x1, a); x1 ^= x0;                      \
    x0 += x1; x1 = TF_ROT(x1, b); x1 ^= x0;                      \
    x0 += x1; x1 = TF_ROT(x1, c); x1 ^= x0;                      \
    x0 += x1; x1 = TF_ROT(x1, d); x1 ^= x0;
    TF_R4(13, 15, 26, 6);  x0 += ks1; x1 += ks2 + 1u;
    TF_R4(17, 29, 16, 24); x0 += ks2; x1 += ks0 + 2u;
    TF_R4(13, 15, 26, 6);  x0 += ks0; x1 += ks1 + 3u;
    TF_R4(17, 29, 16, 24); x0 += ks1; x1 += ks2 + 4u;
    TF_R4(13, 15, 26, 6);  x0 += ks2; x1 += ks0 + 5u;
#undef TF_R4
#undef TF_ROT
    unsigned bits = x0 ^ x1;
    unsigned fb = (bits >> 9) | 0x3F800000u;
    float f01 = __uint_as_float(fb) - 1.0f;
    const float lo = -0.99999994f;
    float u = f01 * 2.0f + lo;
    u = fmaxf(u, lo);
    return 1.4142135f * erfinvf(u);
}

// ---------------------------------------------------------------------------
// k5: faction sync + debate + coop pull + noise + clamp
// ---------------------------------------------------------------------------
__global__ void __launch_bounds__(256) k5_final(const int* __restrict__ last_action,
                                                const int* __restrict__ step,
                                                float* __restrict__ out) {
    const int i = blockIdx.x;
    const int j = threadIdx.x;
    float v = g_newh[(size_t)i * 256 + j];
    const int f = i >> 14;
    v = 0.85f * v + 0.15f * g_fmean[f * 256 + j];
    if (*step > 5 && (i & (FS - 1)) < DC)
        v = 0.85f * v + 0.15f * g_globalop[j];
    const int act = last_action[i];
    if (act != 0) {
        v += 0.05f * (g_gmean[j] - v);
    } else {
        unsigned e = (unsigned)i * 256u + (unsigned)j;
        v += 0.02f * threefry_normal(e);
    }
    v = fminf(fmaxf(v, -10.f), 10.f);
    out[129 + (size_t)i * 256 + j] = v;
}

// ---------------------------------------------------------------------------
#define SMEM_DYN (3 * STAGEB)   // 98304 B

extern "C" void kernel_launch(void* const* d_in, const int* in_sizes, int n_in,
                              void* d_out, int out_size) {
    const float* x        = (const float*)d_in[0];
    const float* payoffs  = (const float*)d_in[1];
    const int*   last_act = (const int*)d_in[2];
    const int*   step     = (const int*)d_in[3];
    const float* hiddens  = (const float*)d_in[4];
    const float* a_w1 = (const float*)d_in[5];
    const float* a_b1 = (const float*)d_in[6];
    const float* a_w2 = (const float*)d_in[7];
    const float* a_b2 = (const float*)d_in[8];
    const float* g_w1 = (const float*)d_in[9];
    const float* g_b1 = (const float*)d_in[10];
    const float* g_w2 = (const float*)d_in[11];
    const float* g_b2 = (const float*)d_in[12];
    const float* gru_wih = (const float*)d_in[13];
    const float* gru_whh = (const float*)d_in[14];
    const float* gru_bih = (const float*)d_in[15];
    const float* gru_bhh = (const float*)d_in[16];
    const float* head_w  = (const float*)d_in[17];
    const float* head_b  = (const float*)d_in[18];
    float* out = (float*)d_out;

    cudaFuncSetAttribute(gemm_hl<1>, cudaFuncAttributeMaxDynamicSharedMemorySize, SMEM_DYN);
    cudaFuncSetAttribute(gemm_hl<2>, cudaFuncAttributeMaxDynamicSharedMemorySize, SMEM_DYN);
    cudaFuncSetAttribute(gemm_hl<3>, cudaFuncAttributeMaxDynamicSharedMemorySize, SMEM_DYN);

    k0_init<<<1, 256>>>(x, a_w1, a_b1, g_w1, g_b1);
    kconv<<<1924, 256>>>(a_w1, g_w1, a_w2, g_w2, gru_wih, gru_whh, gru_bih, gru_bhh);
    khh<<<NCELLS * 256 / (256 * 8), 256>>>(hiddens);
    gemm_hl<1><<<dim3(2, NCELLS / 128), 256, SMEM_DYN>>>(nullptr, nullptr);
    gemm_hl<2><<<dim3(1, NCELLS / 128), 256, SMEM_DYN>>>(a_b2, g_b2);
    gemm_hl<3><<<dim3(8, NCELLS / 128), 256, SMEM_DYN>>>(nullptr, nullptr);
    k3c_gates<<<NCELLS / 128, 256>>>(hiddens, payoffs);
    k4_small<<<1, 256>>>(step, head_w, head_b, out);
    k5_final<<<NCELLS, 256>>>(last_act, step, out);
}